// round 1
// baseline (speedup 1.0000x reference)
#include <cuda_runtime.h>

// SpectralConv2D reduced form:
//   up[b,n]   = mean_c inputs[b,n,c]                     (B=64, N=1024)
//   base[f,p] = omega[f,i,j] * (lambda_in[i]-lambda_out[j]),  p=i*3+j
//   out[b,l,f]= relu( sum_p base[f,p] * (enc[n]-dec[l]) * up[b,n] ),
//               n = (l/30)*32 + (l%30) + (p/3)*32 + (p%3)
// Output layout: (B, 30, 30, F) row-major, F contiguous.

#define B_   64
#define W_   32
#define C_   8
#define F_   64
#define O2_  30
#define L_   900
#define N_   1024

__global__ __launch_bounds__(256, 2)
void spectral_conv_kernel(
    const float* __restrict__ inputs,      // (B, 32, 32, 8)
    const float* __restrict__ omega_diag,  // (F, 3)
    const float* __restrict__ omega_triu,  // (1, F*3)
    const float* __restrict__ omega_tril,  // (1, F*3)
    const float* __restrict__ lambda_in,   // (3, 1)
    const float* __restrict__ lambda_out,  // (1, 3)
    const float* __restrict__ use_encode,  // (1, N)
    const float* __restrict__ use_decode,  // (L, 1)
    float* __restrict__ out)               // (B, 30, 30, F)
{
    __shared__ float up_s[N_];
    __shared__ float enc_s[N_];
    __shared__ float base_s[F_ * 9];

    const int tid = threadIdx.x;
    const int b   = blockIdx.x;

    // ---- channel-mean reduction: 4 pixels per thread, 2x float4 per pixel ----
    const float* inb = inputs + (size_t)b * (N_ * C_);
    #pragma unroll
    for (int i = 0; i < 4; i++) {
        int n = tid + i * 256;
        const float4* p = (const float4*)(inb + n * C_);
        float4 v0 = p[0];
        float4 v1 = p[1];
        up_s[n] = (v0.x + v0.y + v0.z + v0.w + v1.x + v1.y + v1.z + v1.w) * 0.125f;
        enc_s[n] = use_encode[n];
    }

    // ---- assemble base[f][p] = omega * (lam_in[i]-lam_out[j]) ----
    for (int idx = tid; idx < F_ * 9; idx += 256) {
        int f = idx / 9;
        int p = idx - f * 9;
        int i = p / 3, j = p - i * 3;
        float w;
        if (i == j) {
            w = omega_diag[f * 3 + i];
        } else if (i < j) {
            // triu order: (0,1)->0 (0,2)->1 (1,2)->2
            int t = (i == 0) ? (j - 1) : 2;
            w = omega_triu[f * 3 + t];
        } else {
            // tril order: (1,0)->0 (2,0)->1 (2,1)->2
            int t = (i == 1) ? 0 : (1 + j);
            w = omega_tril[f * 3 + t];
        }
        base_s[idx] = w * (lambda_in[i] - lambda_out[j]);
    }
    __syncthreads();

    // ---- each thread owns one output position l (all 64 filters) ----
    int l = blockIdx.y * 256 + tid;
    if (l >= L_) return;

    int r = l / O2_;
    int c = l - r * O2_;
    int start = r * W_ + c;
    float dec = use_decode[l];

    float y[9];
    #pragma unroll
    for (int p = 0; p < 9; p++) {
        int n = start + (p / 3) * W_ + (p % 3);
        y[p] = (enc_s[n] - dec) * up_s[n];
    }

    float* o = out + ((size_t)b * L_ + l) * F_;
    #pragma unroll
    for (int f4 = 0; f4 < F_ / 4; f4++) {
        float4 acc;
        float* a = (float*)&acc;
        #pragma unroll
        for (int q = 0; q < 4; q++) {
            int f = f4 * 4 + q;
            float s = 0.f;
            #pragma unroll
            for (int p = 0; p < 9; p++)
                s = fmaf(base_s[f * 9 + p], y[p], s);
            a[q] = fmaxf(s, 0.f);
        }
        ((float4*)o)[f4] = acc;
    }
}

extern "C" void kernel_launch(void* const* d_in, const int* in_sizes, int n_in,
                              void* d_out, int out_size) {
    (void)in_sizes; (void)n_in; (void)out_size;
    const float* inputs      = (const float*)d_in[0];
    const float* omega_diag  = (const float*)d_in[1];
    const float* omega_triu  = (const float*)d_in[2];
    const float* omega_tril  = (const float*)d_in[3];
    const float* lambda_in   = (const float*)d_in[4];
    const float* lambda_out  = (const float*)d_in[5];
    const float* use_encode  = (const float*)d_in[6];
    const float* use_decode  = (const float*)d_in[7];
    float* out = (float*)d_out;

    dim3 grid(B_, (L_ + 255) / 256);  // (64, 4)
    spectral_conv_kernel<<<grid, 256>>>(
        inputs, omega_diag, omega_triu, omega_tril,
        lambda_in, lambda_out, use_encode, use_decode, out);
}